// round 9
// baseline (speedup 1.0000x reference)
#include <cuda_runtime.h>
#include <cuda_bf16.h>
#include <math.h>
#include <stdint.h>

// Problem constants
#define BB   32
#define CC   256
#define CQ   64
#define HW   4096                 // 64*64
#define CHW  (CC*HW)              // 1048576
#define DD   (CQ*HW)              // 262144

// Scratch (device globals — no allocation allowed)
__device__ float g_Q[(size_t)BB*CQ*HW];
__device__ float g_K[(size_t)BB*CQ*HW];
__device__ float g_energy[BB*BB];
__device__ float g_att[BB*BB];
__device__ uint4 g_y_bf[(size_t)BB*CHW/8];    // bf16 [i][c][p]
__device__ uint4 g_Wv_bf[CC*CC/8];            // bf16 [o][c]

// tf32-split weights for Q/K: [c][o]
__device__ float g_WqT_h[CC*CQ], g_WqT_l[CC*CQ];
__device__ float g_WkT_h[CC*CQ], g_WkT_l[CC*CQ];

// ---------------------------------------------------------------------------
__device__ __forceinline__ float tf32r(float x) {
    uint32_t u;
    asm("cvt.rna.tf32.f32 %0, %1;" : "=r"(u) : "f"(x));
    return __uint_as_float(u);
}

__device__ __forceinline__ void mma_tf32(
    float& c0, float& c1, float& c2, float& c3,
    uint32_t a0, uint32_t a1, uint32_t a2, uint32_t a3,
    uint32_t b0, uint32_t b1)
{
    asm volatile(
        "mma.sync.aligned.m16n8k8.row.col.f32.tf32.tf32.f32 "
        "{%0,%1,%2,%3}, {%4,%5,%6,%7}, {%8,%9}, {%0,%1,%2,%3};"
        : "+f"(c0), "+f"(c1), "+f"(c2), "+f"(c3)
        : "r"(a0), "r"(a1), "r"(a2), "r"(a3), "r"(b0), "r"(b1));
}

__device__ __forceinline__ void mma_bf16(
    float* c, const uint32_t* a, uint32_t b0, uint32_t b1)
{
    asm volatile(
        "mma.sync.aligned.m16n8k16.row.col.f32.bf16.bf16.f32 "
        "{%0,%1,%2,%3}, {%4,%5,%6,%7}, {%8,%9}, {%0,%1,%2,%3};"
        : "+f"(c[0]), "+f"(c[1]), "+f"(c[2]), "+f"(c[3])
        : "r"(a[0]), "r"(a[1]), "r"(a[2]), "r"(a[3]), "r"(b0), "r"(b1));
}

__device__ __forceinline__ void ldsm_x4(
    uint32_t& r0, uint32_t& r1, uint32_t& r2, uint32_t& r3, uint32_t addr)
{
    asm volatile("ldmatrix.sync.aligned.m8n8.x4.shared.b16 {%0,%1,%2,%3}, [%4];"
        : "=r"(r0), "=r"(r1), "=r"(r2), "=r"(r3) : "r"(addr));
}

__device__ __forceinline__ void ldsm_x4_t(
    uint32_t& r0, uint32_t& r1, uint32_t& r2, uint32_t& r3, uint32_t addr)
{
    asm volatile("ldmatrix.sync.aligned.m8n8.x4.trans.shared.b16 {%0,%1,%2,%3}, [%4];"
        : "=r"(r0), "=r"(r1), "=r"(r2), "=r"(r3) : "r"(addr));
}

// ---------------------------------------------------------------------------
// Weight prep: Wq/Wk -> transposed tf32 hi/lo split; Wv -> bf16 [o][c].
__global__ __launch_bounds__(256) void k_prep(
    const float* __restrict__ Wq, const float* __restrict__ Wk,
    const float* __restrict__ Wv)
{
    int t = blockIdx.x * 256 + threadIdx.x;
    int stride = gridDim.x * 256;
    for (int i = t; i < CQ*CC; i += stride) {
        int o = i >> 8, c = i & 255;
        float q = Wq[i];
        float qh = tf32r(q);
        g_WqT_h[c*CQ + o] = qh;
        g_WqT_l[c*CQ + o] = tf32r(q - qh);
        float k = Wk[i];
        float kh = tf32r(k);
        g_WkT_h[c*CQ + o] = kh;
        g_WkT_l[c*CQ + o] = tf32r(k - kh);
    }
    __nv_bfloat16* wv = (__nv_bfloat16*)g_Wv_bf;
    for (int i = t; i < CC*CC; i += stride)
        wv[i] = __float2bfloat16(Wv[i]);
}

// ---------------------------------------------------------------------------
__global__ void k_zero_energy() {
    int t = threadIdx.x;
    if (t < BB*BB) g_energy[t] = 0.0f;
}

// ---------------------------------------------------------------------------
// Q = Wq x0 + bq ; K = Wk x1 + bk via 3xTF32 mma.
// Block: 64 o x 256 p, 8 warps, warp tile m32(p) x n64(o).
__global__ __launch_bounds__(256) void k_proj_tf32(
    const float* __restrict__ x0, const float* __restrict__ x1,
    const float* __restrict__ bq, const float* __restrict__ bk)
{
    const int which = blockIdx.z;
    const float* __restrict__ x    = which ? x1 : x0;
    const float* __restrict__ bias = which ? bk : bq;
    const float* __restrict__ WT_h = which ? g_WkT_h : g_WqT_h;
    const float* __restrict__ WT_l = which ? g_WkT_l : g_WqT_l;
    float* __restrict__ outp       = which ? g_K : g_Q;

    const int b  = blockIdx.y;
    const int p0 = blockIdx.x * 256;
    const int t    = threadIdx.x;
    const int lane = t & 31;
    const int warp = t >> 5;
    const int gid  = lane >> 2;
    const int tig  = lane & 3;
    const int pbase = warp * 32;

    // smem union: xs_h[16][264], xs_l[16][264], ws_h[16][72], ws_l[16][72]
    //             / stage[64][132]
    __shared__ float sm[10752];
    float* xs_h = sm;                  // 4224
    float* xs_l = sm + 4224;           // 4224
    float* ws_h = sm + 8448;           // 1152
    float* ws_l = sm + 9600;           // 1152
    float* stage = sm;                 // 8448

    float C[2][8][4];
    #pragma unroll
    for (int mf = 0; mf < 2; mf++)
        #pragma unroll
        for (int nf = 0; nf < 8; nf++)
            #pragma unroll
            for (int i = 0; i < 4; i++) C[mf][nf][i] = 0.0f;

    const float* xb = x + (size_t)b * CHW + p0;

    for (int cc = 0; cc < CC; cc += 16) {
        __syncthreads();
        // xs: 16c x 256p = 1024 float4 -> 4/thread, tf32 hi/lo split
        #pragma unroll
        for (int r = 0; r < 4; r++) {
            int idx = r * 256 + t;
            int c = idx >> 6, q4 = idx & 63;
            float4 v = *reinterpret_cast<const float4*>(xb + (size_t)(cc + c) * HW + q4 * 4);
            float4 h, l;
            h.x = tf32r(v.x); l.x = tf32r(v.x - h.x);
            h.y = tf32r(v.y); l.y = tf32r(v.y - h.y);
            h.z = tf32r(v.z); l.z = tf32r(v.z - h.z);
            h.w = tf32r(v.w); l.w = tf32r(v.w - h.w);
            *reinterpret_cast<float4*>(&xs_h[c*264 + q4*4]) = h;
            *reinterpret_cast<float4*>(&xs_l[c*264 + q4*4]) = l;
        }
        // ws: 16c x 64o = 256 float4 -> 1/thread (hi and lo)
        {
            int c = t >> 4, q4 = t & 15;
            *reinterpret_cast<float4*>(&ws_h[c*72 + q4*4]) =
                *reinterpret_cast<const float4*>(&WT_h[(cc + c)*CQ + q4*4]);
            *reinterpret_cast<float4*>(&ws_l[c*72 + q4*4]) =
                *reinterpret_cast<const float4*>(&WT_l[(cc + c)*CQ + q4*4]);
        }
        __syncthreads();

        #pragma unroll
        for (int kk = 0; kk < 2; kk++) {
            const int kb = kk * 8;
            const int ar0 = (kb + tig) * 264;
            const int ar2 = (kb + tig + 4) * 264;
            uint32_t Ah[2][4], Al[2][4];
            #pragma unroll
            for (int mf = 0; mf < 2; mf++) {
                const int pc = pbase + mf * 16 + gid;
                Ah[mf][0] = __float_as_uint(xs_h[ar0 + pc]);
                Ah[mf][1] = __float_as_uint(xs_h[ar0 + pc + 8]);
                Ah[mf][2] = __float_as_uint(xs_h[ar2 + pc]);
                Ah[mf][3] = __float_as_uint(xs_h[ar2 + pc + 8]);
                Al[mf][0] = __float_as_uint(xs_l[ar0 + pc]);
                Al[mf][1] = __float_as_uint(xs_l[ar0 + pc + 8]);
                Al[mf][2] = __float_as_uint(xs_l[ar2 + pc]);
                Al[mf][3] = __float_as_uint(xs_l[ar2 + pc + 8]);
            }
            const int br0 = (kb + tig) * 72;
            const int br1 = (kb + tig + 4) * 72;
            #pragma unroll
            for (int nf = 0; nf < 8; nf++) {
                const int bo = nf * 8 + gid;
                uint32_t b0h = __float_as_uint(ws_h[br0 + bo]);
                uint32_t b1h = __float_as_uint(ws_h[br1 + bo]);
                uint32_t b0l = __float_as_uint(ws_l[br0 + bo]);
                uint32_t b1l = __float_as_uint(ws_l[br1 + bo]);
                #pragma unroll
                for (int mf = 0; mf < 2; mf++) {
                    mma_tf32(C[mf][nf][0], C[mf][nf][1], C[mf][nf][2], C[mf][nf][3],
                             Ah[mf][0], Ah[mf][1], Ah[mf][2], Ah[mf][3], b0h, b1h);
                    mma_tf32(C[mf][nf][0], C[mf][nf][1], C[mf][nf][2], C[mf][nf][3],
                             Ah[mf][0], Ah[mf][1], Ah[mf][2], Ah[mf][3], b0l, b1l);
                    mma_tf32(C[mf][nf][0], C[mf][nf][1], C[mf][nf][2], C[mf][nf][3],
                             Al[mf][0], Al[mf][1], Al[mf][2], Al[mf][3], b0h, b1h);
                }
            }
        }
    }

    // Epilogue in two p-half phases through stage[64][132]
    #pragma unroll
    for (int h = 0; h < 2; h++) {
        __syncthreads();
        if ((warp >> 2) == h) {
            const int lp0 = pbase - h * 128;
            #pragma unroll
            for (int mf = 0; mf < 2; mf++)
                #pragma unroll
                for (int nf = 0; nf < 8; nf++) {
                    int o = nf * 8 + tig * 2;
                    int lp = lp0 + mf * 16 + gid;
                    stage[o*132 + lp]         = C[mf][nf][0];
                    stage[(o+1)*132 + lp]     = C[mf][nf][1];
                    stage[o*132 + lp + 8]     = C[mf][nf][2];
                    stage[(o+1)*132 + lp + 8] = C[mf][nf][3];
                }
        }
        __syncthreads();
        #pragma unroll
        for (int r = 0; r < 32; r++) {
            int idx = r * 256 + t;
            int o = idx >> 7, p = idx & 127;
            outp[((size_t)b * CQ + o) * HW + p0 + h*128 + p] = stage[o*132 + p] + bias[o];
        }
    }
}

// ---------------------------------------------------------------------------
// energy[i][j] += sum_d K[i,d] * Q[j,d].  64 thr/block, 4x4 register tile,
// direct float4 LDG (broadcast-coalesced), no smem.
__global__ __launch_bounds__(64) void k_energy()
{
    const int t  = threadIdx.x;
    const int tj = t & 7;
    const int ti = t >> 3;
    const int d0 = blockIdx.x * 512;

    float acc[4][4];
    #pragma unroll
    for (int r = 0; r < 4; r++)
        #pragma unroll
        for (int s = 0; s < 4; s++) acc[r][s] = 0.0f;

    for (int d = d0; d < d0 + 512; d += 4) {
        float4 kv[4], qv[4];
        #pragma unroll
        for (int r = 0; r < 4; r++)
            kv[r] = *reinterpret_cast<const float4*>(&g_K[(size_t)(ti + 8*r) * DD + d]);
        #pragma unroll
        for (int s = 0; s < 4; s++)
            qv[s] = *reinterpret_cast<const float4*>(&g_Q[(size_t)(tj + 8*s) * DD + d]);
        #pragma unroll
        for (int r = 0; r < 4; r++)
            #pragma unroll
            for (int s = 0; s < 4; s++)
                acc[r][s] += kv[r].x*qv[s].x + kv[r].y*qv[s].y
                           + kv[r].z*qv[s].z + kv[r].w*qv[s].w;
    }
    #pragma unroll
    for (int r = 0; r < 4; r++)
        #pragma unroll
        for (int s = 0; s < 4; s++)
            atomicAdd(&g_energy[(ti + 8*r) * BB + (tj + 8*s)], acc[r][s]);
}

// ---------------------------------------------------------------------------
__global__ void k_softmax(float* __restrict__ att_out)
{
    int i = threadIdx.x;
    if (i >= BB) return;
    float e[BB];
    float m = -INFINITY;
    #pragma unroll
    for (int j = 0; j < BB; j++) { e[j] = g_energy[i*BB + j]; m = fmaxf(m, e[j]); }
    float s = 0.f;
    #pragma unroll
    for (int j = 0; j < BB; j++) { e[j] = expf(e[j] - m); s += e[j]; }
    float inv = 1.0f / s;
    #pragma unroll
    for (int j = 0; j < BB; j++) {
        float a = e[j] * inv;
        g_att[i*BB + j] = a;
        if (att_out) att_out[i*BB + j] = a;
    }
}

// ---------------------------------------------------------------------------
// y[i,cp] = sum_j att[i,j] * x0[j,cp]; write bf16.
__global__ __launch_bounds__(256) void k_mix(const float* __restrict__ x0)
{
    __shared__ float att_s[BB*BB];
    const int t = threadIdx.x;
    #pragma unroll
    for (int r = 0; r < 4; r++) att_s[r*256 + t] = g_att[r*256 + t];
    __syncthreads();

    const size_t cp = (size_t)blockIdx.x * 256 + t;
    float acc[BB];
    #pragma unroll
    for (int i = 0; i < BB; i++) acc[i] = 0.0f;

    #pragma unroll
    for (int j = 0; j < BB; j++) {
        float v = x0[(size_t)j * CHW + cp];
        #pragma unroll
        for (int i = 0; i < BB; i++) acc[i] += att_s[i*BB + j] * v;
    }
    __nv_bfloat16* y = (__nv_bfloat16*)g_y_bf;
    #pragma unroll
    for (int i = 0; i < BB; i++)
        y[(size_t)i * CHW + cp] = __float2bfloat16(acc[i]);
}

// ---------------------------------------------------------------------------
// out = gamma*(Wv y + bv) + x1 via bf16 m16n8k16 mma + ldmatrix.
// Block: 64 o x 128 p; 8 warps = 2(o) x 4(p); warp tile m32(o) x n32(p).
__global__ __launch_bounds__(256) void k_out_bf16(
    const float* __restrict__ x1, const float* __restrict__ bv,
    const float* __restrict__ gamma, float* __restrict__ outp)
{
    const int b  = blockIdx.y;
    const int ot = blockIdx.z * 64;
    const int p0 = blockIdx.x * 128;
    const int t    = threadIdx.x;
    const int lane = t & 31;
    const int warp = t >> 5;
    const int wo = warp >> 2;       // 0..1
    const int wp = warp & 3;        // 0..3
    const int obase = wo * 32;
    const int pbw   = wp * 32;
    const int gid = lane >> 2;
    const int tig = lane & 3;

    __shared__ __align__(16) uint16_t ws[64*40];   // [o][c] stride 40 bf16 (80B)
    __shared__ __align__(16) uint16_t ys[32*136];  // [c][p] stride 136 bf16 (272B)
    const uint32_t ws_b = (uint32_t)__cvta_generic_to_shared(ws);
    const uint32_t ys_b = (uint32_t)__cvta_generic_to_shared(ys);

    float C[2][4][4];
    #pragma unroll
    for (int mf = 0; mf < 2; mf++)
        #pragma unroll
        for (int nf = 0; nf < 4; nf++)
            #pragma unroll
            for (int i = 0; i < 4; i++) C[mf][nf][i] = 0.0f;

    const __nv_bfloat16* ybase = (const __nv_bfloat16*)g_y_bf + (size_t)b * CHW + p0;
    const __nv_bfloat16* wvb   = (const __nv_bfloat16*)g_Wv_bf;

    for (int cc = 0; cc < CC; cc += 32) {
        __syncthreads();
        // ws: 64 o x 32 c bf16 (one uint4 per thread)
        {
            int row = t >> 2, ch = t & 3;
            *reinterpret_cast<uint4*>(&ws[row*40 + ch*8]) =
                *reinterpret_cast<const uint4*>(wvb + (size_t)(ot + row)*CC + cc + ch*8);
        }
        // ys: 32 c x 128 p bf16 (two uint4 per thread)
        #pragma unroll
        for (int r = 0; r < 2; r++) {
            int idx = r * 256 + t;
            int row = idx >> 4, ch = idx & 15;
            *reinterpret_cast<uint4*>(&ys[row*136 + ch*8]) =
                *reinterpret_cast<const uint4*>(ybase + (size_t)(cc + row)*HW + ch*8);
        }
        __syncthreads();

        #pragma unroll
        for (int kk = 0; kk < 2; kk++) {
            const int rsel = lane & 15;
            const int half = lane >> 4;
            uint32_t A[2][4];
            #pragma unroll
            for (int mf = 0; mf < 2; mf++) {
                uint32_t addr = ws_b + (uint32_t)((obase + mf*16 + rsel)*80 + kk*32 + half*16);
                ldsm_x4(A[mf][0], A[mf][1], A[mf][2], A[mf][3], addr);
            }
            uint32_t Bf[2][4];
            #pragma unroll
            for (int n2 = 0; n2 < 2; n2++) {
                uint32_t addr = ys_b + (uint32_t)((kk*16 + rsel)*272 + (pbw + n2*16 + half*8)*2);
                ldsm_x4_t(Bf[n2][0], Bf[n2][1], Bf[n2][2], Bf[n2][3], addr);
            }
            #pragma unroll
            for (int mf = 0; mf < 2; mf++)
                #pragma unroll
                for (int nf = 0; nf < 4; nf++)
                    mma_bf16(C[mf][nf], A[mf],
                             Bf[nf>>1][(nf&1)*2], Bf[nf>>1][(nf&1)*2 + 1]);
        }
    }

    const float g = gamma[0];
    #pragma unroll
    for (int mf = 0; mf < 2; mf++) {
        const int o = ot + obase + mf*16 + gid;
        const float bv0 = bv[o], bv1 = bv[o + 8];
        #pragma unroll
        for (int nf = 0; nf < 4; nf++) {
            const int p = p0 + pbw + nf*8 + tig*2;
            size_t gi0 = ((size_t)b * CC + o) * HW + p;
            size_t gi1 = gi0 + (size_t)8 * HW;
            float2 xa = *reinterpret_cast<const float2*>(&x1[gi0]);
            float2 xc = *reinterpret_cast<const float2*>(&x1[gi1]);
            float2 r0, r1;
            r0.x = g * (C[mf][nf][0] + bv0) + xa.x;
            r0.y = g * (C[mf][nf][1] + bv0) + xa.y;
            r1.x = g * (C[mf][nf][2] + bv1) + xc.x;
            r1.y = g * (C[mf][nf][3] + bv1) + xc.y;
            *reinterpret_cast<float2*>(&outp[gi0]) = r0;
            *reinterpret_cast<float2*>(&outp[gi1]) = r1;
        }
    }
}

// ---------------------------------------------------------------------------
extern "C" void kernel_launch(void* const* d_in, const int* in_sizes, int n_in,
                              void* d_out, int out_size)
{
    const float* x0    = (const float*)d_in[0];
    const float* x1    = (const float*)d_in[1];
    const float* Wq    = (const float*)d_in[2];
    const float* bq    = (const float*)d_in[3];
    const float* Wk    = (const float*)d_in[4];
    const float* bk    = (const float*)d_in[5];
    const float* Wv    = (const float*)d_in[6];
    const float* bv    = (const float*)d_in[7];
    const float* gamma = (const float*)d_in[8];
    float* out = (float*)d_out;

    const long long out_elems = (long long)BB * CC * HW;
    float* att_out = ((long long)out_size >= out_elems + BB*BB)
                     ? out + out_elems : nullptr;

    k_prep<<<32, 256>>>(Wq, Wk, Wv);
    k_zero_energy<<<1, 1024>>>();
    k_proj_tf32<<<dim3(HW/256, BB, 2), 256>>>(x0, x1, bq, bk);
    k_energy<<<DD/512, 64>>>();
    k_softmax<<<1, 32>>>(att_out);
    k_mix<<<CHW/256, 256>>>(x0);
    k_out_bf16<<<dim3(HW/128, BB, CC/64), 256>>>(x1, bv, gamma, out);
}

// round 10
// speedup vs baseline: 1.0518x; 1.0518x over previous
#include <cuda_runtime.h>
#include <cuda_bf16.h>
#include <cuda_fp16.h>
#include <math.h>
#include <stdint.h>

// Problem constants
#define BB   32
#define CC   256
#define CQ   64
#define HW   4096                 // 64*64
#define CHW  (CC*HW)              // 1048576
#define DD   (CQ*HW)              // 262144

// Scratch (device globals — no allocation allowed)
__device__ __half g_Qh[(size_t)BB*DD];        // fp16 [b][o][p]
__device__ __half g_Kh[(size_t)BB*DD];
__device__ float g_energy[BB*BB];
__device__ float g_att[BB*BB];
__device__ uint4 g_y_bf[(size_t)BB*CHW/8];    // bf16 [i][c][p]
__device__ uint4 g_Wv_bf[CC*CC/8];            // bf16 [o][c]

// tf32-split weights for Q/K: [c][o]
__device__ float g_WqT_h[CC*CQ], g_WqT_l[CC*CQ];
__device__ float g_WkT_h[CC*CQ], g_WkT_l[CC*CQ];

// ---------------------------------------------------------------------------
__device__ __forceinline__ float tf32r(float x) {
    uint32_t u;
    asm("cvt.rna.tf32.f32 %0, %1;" : "=r"(u) : "f"(x));
    return __uint_as_float(u);
}

__device__ __forceinline__ void mma_tf32(
    float& c0, float& c1, float& c2, float& c3,
    uint32_t a0, uint32_t a1, uint32_t a2, uint32_t a3,
    uint32_t b0, uint32_t b1)
{
    asm volatile(
        "mma.sync.aligned.m16n8k8.row.col.f32.tf32.tf32.f32 "
        "{%0,%1,%2,%3}, {%4,%5,%6,%7}, {%8,%9}, {%0,%1,%2,%3};"
        : "+f"(c0), "+f"(c1), "+f"(c2), "+f"(c3)
        : "r"(a0), "r"(a1), "r"(a2), "r"(a3), "r"(b0), "r"(b1));
}

__device__ __forceinline__ void mma_bf16(
    float* c, const uint32_t* a, uint32_t b0, uint32_t b1)
{
    asm volatile(
        "mma.sync.aligned.m16n8k16.row.col.f32.bf16.bf16.f32 "
        "{%0,%1,%2,%3}, {%4,%5,%6,%7}, {%8,%9}, {%0,%1,%2,%3};"
        : "+f"(c[0]), "+f"(c[1]), "+f"(c[2]), "+f"(c[3])
        : "r"(a[0]), "r"(a[1]), "r"(a[2]), "r"(a[3]), "r"(b0), "r"(b1));
}

__device__ __forceinline__ void ldsm_x4(
    uint32_t& r0, uint32_t& r1, uint32_t& r2, uint32_t& r3, uint32_t addr)
{
    asm volatile("ldmatrix.sync.aligned.m8n8.x4.shared.b16 {%0,%1,%2,%3}, [%4];"
        : "=r"(r0), "=r"(r1), "=r"(r2), "=r"(r3) : "r"(addr));
}

__device__ __forceinline__ void ldsm_x4_t(
    uint32_t& r0, uint32_t& r1, uint32_t& r2, uint32_t& r3, uint32_t addr)
{
    asm volatile("ldmatrix.sync.aligned.m8n8.x4.trans.shared.b16 {%0,%1,%2,%3}, [%4];"
        : "=r"(r0), "=r"(r1), "=r"(r2), "=r"(r3) : "r"(addr));
}

// ---------------------------------------------------------------------------
// Weight prep: Wq/Wk -> transposed tf32 hi/lo split; Wv -> bf16 [o][c].
__global__ __launch_bounds__(256) void k_prep(
    const float* __restrict__ Wq, const float* __restrict__ Wk,
    const float* __restrict__ Wv)
{
    int t = blockIdx.x * 256 + threadIdx.x;
    int stride = gridDim.x * 256;
    for (int i = t; i < CQ*CC; i += stride) {
        int o = i >> 8, c = i & 255;
        float q = Wq[i];
        float qh = tf32r(q);
        g_WqT_h[c*CQ + o] = qh;
        g_WqT_l[c*CQ + o] = tf32r(q - qh);
        float k = Wk[i];
        float kh = tf32r(k);
        g_WkT_h[c*CQ + o] = kh;
        g_WkT_l[c*CQ + o] = tf32r(k - kh);
    }
    __nv_bfloat16* wv = (__nv_bfloat16*)g_Wv_bf;
    for (int i = t; i < CC*CC; i += stride)
        wv[i] = __float2bfloat16(Wv[i]);
}

// ---------------------------------------------------------------------------
__global__ void k_zero_energy() {
    int t = threadIdx.x;
    if (t < BB*BB) g_energy[t] = 0.0f;
}

// ---------------------------------------------------------------------------
// Q = Wq x0 + bq ; K = Wk x1 + bk via 3xTF32 mma.
// Block: 64 o x 256 p, 8 warps, warp tile m32(p) x n64(o). fp16 output.
__global__ __launch_bounds__(256) void k_proj_tf32(
    const float* __restrict__ x0, const float* __restrict__ x1,
    const float* __restrict__ bq, const float* __restrict__ bk)
{
    const int which = blockIdx.z;
    const float* __restrict__ x    = which ? x1 : x0;
    const float* __restrict__ bias = which ? bk : bq;
    const float* __restrict__ WT_h = which ? g_WkT_h : g_WqT_h;
    const float* __restrict__ WT_l = which ? g_WkT_l : g_WqT_l;
    __half* __restrict__ outp      = which ? g_Kh : g_Qh;

    const int b  = blockIdx.y;
    const int p0 = blockIdx.x * 256;
    const int t    = threadIdx.x;
    const int lane = t & 31;
    const int warp = t >> 5;
    const int gid  = lane >> 2;
    const int tig  = lane & 3;
    const int pbase = warp * 32;

    __shared__ float sm[10752];
    float* xs_h = sm;                  // [16][264]
    float* xs_l = sm + 4224;
    float* ws_h = sm + 8448;           // [16][72]
    float* ws_l = sm + 9600;
    float* stage = sm;                 // [64][132]

    float C[2][8][4];
    #pragma unroll
    for (int mf = 0; mf < 2; mf++)
        #pragma unroll
        for (int nf = 0; nf < 8; nf++)
            #pragma unroll
            for (int i = 0; i < 4; i++) C[mf][nf][i] = 0.0f;

    const float* xb = x + (size_t)b * CHW + p0;

    for (int cc = 0; cc < CC; cc += 16) {
        __syncthreads();
        #pragma unroll
        for (int r = 0; r < 4; r++) {
            int idx = r * 256 + t;
            int c = idx >> 6, q4 = idx & 63;
            float4 v = *reinterpret_cast<const float4*>(xb + (size_t)(cc + c) * HW + q4 * 4);
            float4 h, l;
            h.x = tf32r(v.x); l.x = tf32r(v.x - h.x);
            h.y = tf32r(v.y); l.y = tf32r(v.y - h.y);
            h.z = tf32r(v.z); l.z = tf32r(v.z - h.z);
            h.w = tf32r(v.w); l.w = tf32r(v.w - h.w);
            *reinterpret_cast<float4*>(&xs_h[c*264 + q4*4]) = h;
            *reinterpret_cast<float4*>(&xs_l[c*264 + q4*4]) = l;
        }
        {
            int c = t >> 4, q4 = t & 15;
            *reinterpret_cast<float4*>(&ws_h[c*72 + q4*4]) =
                *reinterpret_cast<const float4*>(&WT_h[(cc + c)*CQ + q4*4]);
            *reinterpret_cast<float4*>(&ws_l[c*72 + q4*4]) =
                *reinterpret_cast<const float4*>(&WT_l[(cc + c)*CQ + q4*4]);
        }
        __syncthreads();

        #pragma unroll
        for (int kk = 0; kk < 2; kk++) {
            const int kb = kk * 8;
            const int ar0 = (kb + tig) * 264;
            const int ar2 = (kb + tig + 4) * 264;
            uint32_t Ah[2][4], Al[2][4];
            #pragma unroll
            for (int mf = 0; mf < 2; mf++) {
                const int pc = pbase + mf * 16 + gid;
                Ah[mf][0] = __float_as_uint(xs_h[ar0 + pc]);
                Ah[mf][1] = __float_as_uint(xs_h[ar0 + pc + 8]);
                Ah[mf][2] = __float_as_uint(xs_h[ar2 + pc]);
                Ah[mf][3] = __float_as_uint(xs_h[ar2 + pc + 8]);
                Al[mf][0] = __float_as_uint(xs_l[ar0 + pc]);
                Al[mf][1] = __float_as_uint(xs_l[ar0 + pc + 8]);
                Al[mf][2] = __float_as_uint(xs_l[ar2 + pc]);
                Al[mf][3] = __float_as_uint(xs_l[ar2 + pc + 8]);
            }
            const int br0 = (kb + tig) * 72;
            const int br1 = (kb + tig + 4) * 72;
            #pragma unroll
            for (int nf = 0; nf < 8; nf++) {
                const int bo = nf * 8 + gid;
                uint32_t b0h = __float_as_uint(ws_h[br0 + bo]);
                uint32_t b1h = __float_as_uint(ws_h[br1 + bo]);
                uint32_t b0l = __float_as_uint(ws_l[br0 + bo]);
                uint32_t b1l = __float_as_uint(ws_l[br1 + bo]);
                #pragma unroll
                for (int mf = 0; mf < 2; mf++) {
                    mma_tf32(C[mf][nf][0], C[mf][nf][1], C[mf][nf][2], C[mf][nf][3],
                             Ah[mf][0], Ah[mf][1], Ah[mf][2], Ah[mf][3], b0h, b1h);
                    mma_tf32(C[mf][nf][0], C[mf][nf][1], C[mf][nf][2], C[mf][nf][3],
                             Ah[mf][0], Ah[mf][1], Ah[mf][2], Ah[mf][3], b0l, b1l);
                    mma_tf32(C[mf][nf][0], C[mf][nf][1], C[mf][nf][2], C[mf][nf][3],
                             Al[mf][0], Al[mf][1], Al[mf][2], Al[mf][3], b0h, b1h);
                }
            }
        }
    }

    // Epilogue in two p-half phases through stage[64][132]; fp16 out
    #pragma unroll
    for (int h = 0; h < 2; h++) {
        __syncthreads();
        if ((warp >> 2) == h) {
            const int lp0 = pbase - h * 128;
            #pragma unroll
            for (int mf = 0; mf < 2; mf++)
                #pragma unroll
                for (int nf = 0; nf < 8; nf++) {
                    int o = nf * 8 + tig * 2;
                    int lp = lp0 + mf * 16 + gid;
                    stage[o*132 + lp]         = C[mf][nf][0];
                    stage[(o+1)*132 + lp]     = C[mf][nf][1];
                    stage[o*132 + lp + 8]     = C[mf][nf][2];
                    stage[(o+1)*132 + lp + 8] = C[mf][nf][3];
                }
        }
        __syncthreads();
        #pragma unroll
        for (int r = 0; r < 16; r++) {
            int idx = r * 512 + t * 2;
            int o = idx >> 7, p = idx & 127;
            __half2 v = __floats2half2_rn(stage[o*132 + p] + bias[o],
                                          stage[o*132 + p + 1] + bias[o]);
            *reinterpret_cast<__half2*>(
                &outp[((size_t)b * CQ + o) * HW + p0 + h*128 + p]) = v;
        }
    }
}

// ---------------------------------------------------------------------------
// energy[i][j] += sum_d K[i,d]*Q[j,d].  256 blocks x 256 thr, 2x2 tile,
// fp16 uint2 loads (broadcast-coalesced), no smem.
__global__ __launch_bounds__(256) void k_energy()
{
    const int t  = threadIdx.x;
    const int tj = t & 15;
    const int ti = t >> 4;
    const int d0 = blockIdx.x * 1024;

    float acc[2][2] = {{0.f,0.f},{0.f,0.f}};

    #pragma unroll 2
    for (int d = d0; d < d0 + 1024; d += 4) {
        float2 kf[2][2], qf[2][2];
        #pragma unroll
        for (int r = 0; r < 2; r++) {
            uint2 kv = *reinterpret_cast<const uint2*>(&g_Kh[(size_t)(ti + 16*r) * DD + d]);
            kf[r][0] = __half22float2(*reinterpret_cast<__half2*>(&kv.x));
            kf[r][1] = __half22float2(*reinterpret_cast<__half2*>(&kv.y));
        }
        #pragma unroll
        for (int s = 0; s < 2; s++) {
            uint2 qv = *reinterpret_cast<const uint2*>(&g_Qh[(size_t)(tj + 16*s) * DD + d]);
            qf[s][0] = __half22float2(*reinterpret_cast<__half2*>(&qv.x));
            qf[s][1] = __half22float2(*reinterpret_cast<__half2*>(&qv.y));
        }
        #pragma unroll
        for (int r = 0; r < 2; r++)
            #pragma unroll
            for (int s = 0; s < 2; s++)
                acc[r][s] += kf[r][0].x*qf[s][0].x + kf[r][0].y*qf[s][0].y
                           + kf[r][1].x*qf[s][1].x + kf[r][1].y*qf[s][1].y;
    }
    #pragma unroll
    for (int r = 0; r < 2; r++)
        #pragma unroll
        for (int s = 0; s < 2; s++)
            atomicAdd(&g_energy[(ti + 16*r) * BB + (tj + 16*s)], acc[r][s]);
}

// ---------------------------------------------------------------------------
__global__ void k_softmax(float* __restrict__ att_out)
{
    int i = threadIdx.x;
    if (i >= BB) return;
    float e[BB];
    float m = -INFINITY;
    #pragma unroll
    for (int j = 0; j < BB; j++) { e[j] = g_energy[i*BB + j]; m = fmaxf(m, e[j]); }
    float s = 0.f;
    #pragma unroll
    for (int j = 0; j < BB; j++) { e[j] = expf(e[j] - m); s += e[j]; }
    float inv = 1.0f / s;
    #pragma unroll
    for (int j = 0; j < BB; j++) {
        float a = e[j] * inv;
        g_att[i*BB + j] = a;
        if (att_out) att_out[i*BB + j] = a;
    }
}

// ---------------------------------------------------------------------------
// y[i,cp] = sum_j att[i,j]*x0[j,cp]; float2 per thread, packed bf16x2 stores.
__global__ __launch_bounds__(256) void k_mix(const float* __restrict__ x0)
{
    __shared__ float att_s[BB*BB];
    const int t = threadIdx.x;
    #pragma unroll
    for (int r = 0; r < 4; r++) att_s[r*256 + t] = g_att[r*256 + t];
    __syncthreads();

    const size_t cp = ((size_t)blockIdx.x * 256 + t) * 2;
    float2 acc[BB];
    #pragma unroll
    for (int i = 0; i < BB; i++) acc[i] = make_float2(0.f, 0.f);

    #pragma unroll
    for (int j = 0; j < BB; j++) {
        float2 v = *reinterpret_cast<const float2*>(&x0[(size_t)j * CHW + cp]);
        #pragma unroll
        for (int i = 0; i < BB; i++) {
            float a = att_s[i*BB + j];
            acc[i].x += a * v.x;
            acc[i].y += a * v.y;
        }
    }
    uint32_t* y2 = (uint32_t*)g_y_bf;
    const size_t base = (size_t)blockIdx.x * 256 + t;
    #pragma unroll
    for (int i = 0; i < BB; i++) {
        __nv_bfloat162 bv = __floats2bfloat162_rn(acc[i].x, acc[i].y);
        y2[(size_t)i * (CHW/2) + base] = *reinterpret_cast<uint32_t*>(&bv);
    }
}

// ---------------------------------------------------------------------------
// out = gamma*(Wv y + bv) + x1 via bf16 m16n8k16 mma + ldmatrix.
// Block: 64 o x 128 p; 8 warps = 2(o) x 4(p); warp tile m32(o) x n32(p).
__global__ __launch_bounds__(256) void k_out_bf16(
    const float* __restrict__ x1, const float* __restrict__ bv,
    const float* __restrict__ gamma, float* __restrict__ outp)
{
    const int b  = blockIdx.y;
    const int ot = blockIdx.z * 64;
    const int p0 = blockIdx.x * 128;
    const int t    = threadIdx.x;
    const int lane = t & 31;
    const int warp = t >> 5;
    const int wo = warp >> 2;
    const int wp = warp & 3;
    const int obase = wo * 32;
    const int pbw   = wp * 32;
    const int gid = lane >> 2;
    const int tig = lane & 3;

    __shared__ __align__(16) uint16_t ws[64*40];
    __shared__ __align__(16) uint16_t ys[32*136];
    const uint32_t ws_b = (uint32_t)__cvta_generic_to_shared(ws);
    const uint32_t ys_b = (uint32_t)__cvta_generic_to_shared(ys);

    float C[2][4][4];
    #pragma unroll
    for (int mf = 0; mf < 2; mf++)
        #pragma unroll
        for (int nf = 0; nf < 4; nf++)
            #pragma unroll
            for (int i = 0; i < 4; i++) C[mf][nf][i] = 0.0f;

    const __nv_bfloat16* ybase = (const __nv_bfloat16*)g_y_bf + (size_t)b * CHW + p0;
    const __nv_bfloat16* wvb   = (const __nv_bfloat16*)g_Wv_bf;

    for (int cc = 0; cc < CC; cc += 32) {
        __syncthreads();
        {
            int row = t >> 2, ch = t & 3;
            *reinterpret_cast<uint4*>(&ws[row*40 + ch*8]) =
                *reinterpret_cast<const uint4*>(wvb + (size_t)(ot + row)*CC + cc + ch*8);
        }
        #pragma unroll
        for (int r = 0; r < 2; r++) {
            int idx = r * 256 + t;
            int row = idx >> 4, ch = idx & 15;
            *reinterpret_cast<uint4*>(&ys[row*136 + ch*8]) =
                *reinterpret_cast<const uint4*>(ybase + (size_t)(cc + row)*HW + ch*8);
        }
        __syncthreads();

        #pragma unroll
        for (int kk = 0; kk < 2; kk++) {
            const int rsel = lane & 15;
            const int half = lane >> 4;
            uint32_t A[2][4];
            #pragma unroll
            for (int mf = 0; mf < 2; mf++) {
                uint32_t addr = ws_b + (uint32_t)((obase + mf*16 + rsel)*80 + kk*32 + half*16);
                ldsm_x4(A[mf][0], A[mf][1], A[mf][2], A[mf][3], addr);
            }
            uint32_t Bf[2][4];
            #pragma unroll
            for (int n2 = 0; n2 < 2; n2++) {
                uint32_t addr = ys_b + (uint32_t)((kk*16 + rsel)*272 + (pbw + n2*16 + half*8)*2);
                ldsm_x4_t(Bf[n2][0], Bf[n2][1], Bf[n2][2], Bf[n2][3], addr);
            }
            #pragma unroll
            for (int mf = 0; mf < 2; mf++)
                #pragma unroll
                for (int nf = 0; nf < 4; nf++)
                    mma_bf16(C[mf][nf], A[mf],
                             Bf[nf>>1][(nf&1)*2], Bf[nf>>1][(nf&1)*2 + 1]);
        }
    }

    const float g = gamma[0];
    #pragma unroll
    for (int mf = 0; mf < 2; mf++) {
        const int o = ot + obase + mf*16 + gid;
        const float bv0 = bv[o], bv1 = bv[o + 8];
        #pragma unroll
        for (int nf = 0; nf < 4; nf++) {
            const int p = p0 + pbw + nf*8 + tig*2;
            size_t gi0 = ((size_t)b * CC + o) * HW + p;
            size_t gi1 = gi0 + (size_t)8 * HW;
            float2 xa = *reinterpret_cast<const float2*>(&x1[gi0]);
            float2 xc = *reinterpret_cast<const float2*>(&x1[gi1]);
            float2 r0, r1;
            r0.x = g * (C[mf][nf][0] + bv0) + xa.x;
            r0.y = g * (C[mf][nf][1] + bv0) + xa.y;
            r1.x = g * (C[mf][nf][2] + bv1) + xc.x;
            r1.y = g * (C[mf][nf][3] + bv1) + xc.y;
            *reinterpret_cast<float2*>(&outp[gi0]) = r0;
            *reinterpret_cast<float2*>(&outp[gi1]) = r1;
        }
    }
}

// ---------------------------------------------------------------------------
extern "C" void kernel_launch(void* const* d_in, const int* in_sizes, int n_in,
                              void* d_out, int out_size)
{
    const float* x0    = (const float*)d_in[0];
    const float* x1    = (const float*)d_in[1];
    const float* Wq    = (const float*)d_in[2];
    const float* bq    = (const float*)d_in[3];
    const float* Wk    = (const float*)d_in[4];
    const float* bk    = (const float*)d_in[5];
    const float* Wv    = (const float*)d_in[6];
    const float* bv    = (const float*)d_in[7];
    const float* gamma = (const float*)d_in[8];
    float* out = (float*)d_out;

    const long long out_elems = (long long)BB * CC * HW;
    float* att_out = ((long long)out_size >= out_elems + BB*BB)
                     ? out + out_elems : nullptr;

    k_prep<<<32, 256>>>(Wq, Wk, Wv);
    k_zero_energy<<<1, 1024>>>();
    k_proj_tf32<<<dim3(HW/256, BB, 2), 256>>>(x0, x1, bq, bk);
    k_energy<<<DD/1024, 256>>>();
    k_softmax<<<1, 32>>>(att_out);
    k_mix<<<CHW/512, 256>>>(x0);
    k_out_bf16<<<dim3(HW/128, BB, CC/64), 256>>>(x1, bv, gamma, out);
}

// round 11
// speedup vs baseline: 1.3573x; 1.2904x over previous
#include <cuda_runtime.h>
#include <cuda_bf16.h>
#include <cuda_fp16.h>
#include <math.h>
#include <stdint.h>

// Problem constants
#define BB   32
#define CC   256
#define CQ   64
#define HW   4096                 // 64*64
#define CHW  (CC*HW)              // 1048576
#define DD   (CQ*HW)              // 262144

// Scratch (device globals — no allocation allowed)
__device__ __half g_Qh[(size_t)BB*DD];        // fp16 [b][o][p]
__device__ __half g_Kh[(size_t)BB*DD];
__device__ float g_energy[BB*BB];
__device__ float g_att[BB*BB];
__device__ uint4 g_y_bf[(size_t)BB*CHW/8];    // bf16 [i][c][p]
__device__ uint4 g_Wv_bf[CC*CC/8];            // bf16 [o][c]

// tf32-split weights for Q/K: [c][o]
__device__ float g_WqT_h[CC*CQ], g_WqT_l[CC*CQ];
__device__ float g_WkT_h[CC*CQ], g_WkT_l[CC*CQ];

// ---------------------------------------------------------------------------
__device__ __forceinline__ float tf32r(float x) {
    uint32_t u;
    asm("cvt.rna.tf32.f32 %0, %1;" : "=r"(u) : "f"(x));
    return __uint_as_float(u);
}

__device__ __forceinline__ void mma_tf32(
    float& c0, float& c1, float& c2, float& c3,
    uint32_t a0, uint32_t a1, uint32_t a2, uint32_t a3,
    uint32_t b0, uint32_t b1)
{
    asm volatile(
        "mma.sync.aligned.m16n8k8.row.col.f32.tf32.tf32.f32 "
        "{%0,%1,%2,%3}, {%4,%5,%6,%7}, {%8,%9}, {%0,%1,%2,%3};"
        : "+f"(c0), "+f"(c1), "+f"(c2), "+f"(c3)
        : "r"(a0), "r"(a1), "r"(a2), "r"(a3), "r"(b0), "r"(b1));
}

__device__ __forceinline__ void mma_bf16(
    float* c, const uint32_t* a, uint32_t b0, uint32_t b1)
{
    asm volatile(
        "mma.sync.aligned.m16n8k16.row.col.f32.bf16.bf16.f32 "
        "{%0,%1,%2,%3}, {%4,%5,%6,%7}, {%8,%9}, {%0,%1,%2,%3};"
        : "+f"(c[0]), "+f"(c[1]), "+f"(c[2]), "+f"(c[3])
        : "r"(a[0]), "r"(a[1]), "r"(a[2]), "r"(a[3]), "r"(b0), "r"(b1));
}

__device__ __forceinline__ void mma_f16(
    float* c, const uint32_t* a, uint32_t b0, uint32_t b1)
{
    asm volatile(
        "mma.sync.aligned.m16n8k16.row.col.f32.f16.f16.f32 "
        "{%0,%1,%2,%3}, {%4,%5,%6,%7}, {%8,%9}, {%0,%1,%2,%3};"
        : "+f"(c[0]), "+f"(c[1]), "+f"(c[2]), "+f"(c[3])
        : "r"(a[0]), "r"(a[1]), "r"(a[2]), "r"(a[3]), "r"(b0), "r"(b1));
}

__device__ __forceinline__ void ldsm_x4(
    uint32_t& r0, uint32_t& r1, uint32_t& r2, uint32_t& r3, uint32_t addr)
{
    asm volatile("ldmatrix.sync.aligned.m8n8.x4.shared.b16 {%0,%1,%2,%3}, [%4];"
        : "=r"(r0), "=r"(r1), "=r"(r2), "=r"(r3) : "r"(addr));
}

__device__ __forceinline__ void ldsm_x2(
    uint32_t& r0, uint32_t& r1, uint32_t addr)
{
    asm volatile("ldmatrix.sync.aligned.m8n8.x2.shared.b16 {%0,%1}, [%2];"
        : "=r"(r0), "=r"(r1) : "r"(addr));
}

__device__ __forceinline__ void ldsm_x4_t(
    uint32_t& r0, uint32_t& r1, uint32_t& r2, uint32_t& r3, uint32_t addr)
{
    asm volatile("ldmatrix.sync.aligned.m8n8.x4.trans.shared.b16 {%0,%1,%2,%3}, [%4];"
        : "=r"(r0), "=r"(r1), "=r"(r2), "=r"(r3) : "r"(addr));
}

// ---------------------------------------------------------------------------
// Weight prep: Wq/Wk -> transposed tf32 hi/lo split; Wv -> bf16 [o][c].
__global__ __launch_bounds__(256) void k_prep(
    const float* __restrict__ Wq, const float* __restrict__ Wk,
    const float* __restrict__ Wv)
{
    int t = blockIdx.x * 256 + threadIdx.x;
    int stride = gridDim.x * 256;
    for (int i = t; i < CQ*CC; i += stride) {
        int o = i >> 8, c = i & 255;
        float q = Wq[i];
        float qh = tf32r(q);
        g_WqT_h[c*CQ + o] = qh;
        g_WqT_l[c*CQ + o] = tf32r(q - qh);
        float k = Wk[i];
        float kh = tf32r(k);
        g_WkT_h[c*CQ + o] = kh;
        g_WkT_l[c*CQ + o] = tf32r(k - kh);
    }
    __nv_bfloat16* wv = (__nv_bfloat16*)g_Wv_bf;
    for (int i = t; i < CC*CC; i += stride)
        wv[i] = __float2bfloat16(Wv[i]);
}

// ---------------------------------------------------------------------------
__global__ void k_zero_energy() {
    int t = threadIdx.x;
    if (t < BB*BB) g_energy[t] = 0.0f;
}

// ---------------------------------------------------------------------------
// Q = Wq x0 + bq ; K = Wk x1 + bk via 3xTF32 mma.
// Block: 64 o x 256 p, 8 warps, warp tile m32(p) x n64(o). fp16 output.
__global__ __launch_bounds__(256) void k_proj_tf32(
    const float* __restrict__ x0, const float* __restrict__ x1,
    const float* __restrict__ bq, const float* __restrict__ bk)
{
    const int which = blockIdx.z;
    const float* __restrict__ x    = which ? x1 : x0;
    const float* __restrict__ bias = which ? bk : bq;
    const float* __restrict__ WT_h = which ? g_WkT_h : g_WqT_h;
    const float* __restrict__ WT_l = which ? g_WkT_l : g_WqT_l;
    __half* __restrict__ outp      = which ? g_Kh : g_Qh;

    const int b  = blockIdx.y;
    const int p0 = blockIdx.x * 256;
    const int t    = threadIdx.x;
    const int lane = t & 31;
    const int warp = t >> 5;
    const int gid  = lane >> 2;
    const int tig  = lane & 3;
    const int pbase = warp * 32;

    __shared__ float sm[10752];
    float* xs_h = sm;                  // [16][264]
    float* xs_l = sm + 4224;
    float* ws_h = sm + 8448;           // [16][72]
    float* ws_l = sm + 9600;
    float* stage = sm;                 // [64][132]

    float C[2][8][4];
    #pragma unroll
    for (int mf = 0; mf < 2; mf++)
        #pragma unroll
        for (int nf = 0; nf < 8; nf++)
            #pragma unroll
            for (int i = 0; i < 4; i++) C[mf][nf][i] = 0.0f;

    const float* xb = x + (size_t)b * CHW + p0;

    for (int cc = 0; cc < CC; cc += 16) {
        __syncthreads();
        #pragma unroll
        for (int r = 0; r < 4; r++) {
            int idx = r * 256 + t;
            int c = idx >> 6, q4 = idx & 63;
            float4 v = *reinterpret_cast<const float4*>(xb + (size_t)(cc + c) * HW + q4 * 4);
            float4 h, l;
            h.x = tf32r(v.x); l.x = tf32r(v.x - h.x);
            h.y = tf32r(v.y); l.y = tf32r(v.y - h.y);
            h.z = tf32r(v.z); l.z = tf32r(v.z - h.z);
            h.w = tf32r(v.w); l.w = tf32r(v.w - h.w);
            *reinterpret_cast<float4*>(&xs_h[c*264 + q4*4]) = h;
            *reinterpret_cast<float4*>(&xs_l[c*264 + q4*4]) = l;
        }
        {
            int c = t >> 4, q4 = t & 15;
            *reinterpret_cast<float4*>(&ws_h[c*72 + q4*4]) =
                *reinterpret_cast<const float4*>(&WT_h[(cc + c)*CQ + q4*4]);
            *reinterpret_cast<float4*>(&ws_l[c*72 + q4*4]) =
                *reinterpret_cast<const float4*>(&WT_l[(cc + c)*CQ + q4*4]);
        }
        __syncthreads();

        #pragma unroll
        for (int kk = 0; kk < 2; kk++) {
            const int kb = kk * 8;
            const int ar0 = (kb + tig) * 264;
            const int ar2 = (kb + tig + 4) * 264;
            uint32_t Ah[2][4], Al[2][4];
            #pragma unroll
            for (int mf = 0; mf < 2; mf++) {
                const int pc = pbase + mf * 16 + gid;
                Ah[mf][0] = __float_as_uint(xs_h[ar0 + pc]);
                Ah[mf][1] = __float_as_uint(xs_h[ar0 + pc + 8]);
                Ah[mf][2] = __float_as_uint(xs_h[ar2 + pc]);
                Ah[mf][3] = __float_as_uint(xs_h[ar2 + pc + 8]);
                Al[mf][0] = __float_as_uint(xs_l[ar0 + pc]);
                Al[mf][1] = __float_as_uint(xs_l[ar0 + pc + 8]);
                Al[mf][2] = __float_as_uint(xs_l[ar2 + pc]);
                Al[mf][3] = __float_as_uint(xs_l[ar2 + pc + 8]);
            }
            const int br0 = (kb + tig) * 72;
            const int br1 = (kb + tig + 4) * 72;
            #pragma unroll
            for (int nf = 0; nf < 8; nf++) {
                const int bo = nf * 8 + gid;
                uint32_t b0h = __float_as_uint(ws_h[br0 + bo]);
                uint32_t b1h = __float_as_uint(ws_h[br1 + bo]);
                uint32_t b0l = __float_as_uint(ws_l[br0 + bo]);
                uint32_t b1l = __float_as_uint(ws_l[br1 + bo]);
                #pragma unroll
                for (int mf = 0; mf < 2; mf++) {
                    mma_tf32(C[mf][nf][0], C[mf][nf][1], C[mf][nf][2], C[mf][nf][3],
                             Ah[mf][0], Ah[mf][1], Ah[mf][2], Ah[mf][3], b0h, b1h);
                    mma_tf32(C[mf][nf][0], C[mf][nf][1], C[mf][nf][2], C[mf][nf][3],
                             Ah[mf][0], Ah[mf][1], Ah[mf][2], Ah[mf][3], b0l, b1l);
                    mma_tf32(C[mf][nf][0], C[mf][nf][1], C[mf][nf][2], C[mf][nf][3],
                             Al[mf][0], Al[mf][1], Al[mf][2], Al[mf][3], b0h, b1h);
                }
            }
        }
    }

    // Epilogue in two p-half phases through stage[64][132]; fp16 out
    #pragma unroll
    for (int h = 0; h < 2; h++) {
        __syncthreads();
        if ((warp >> 2) == h) {
            const int lp0 = pbase - h * 128;
            #pragma unroll
            for (int mf = 0; mf < 2; mf++)
                #pragma unroll
                for (int nf = 0; nf < 8; nf++) {
                    int o = nf * 8 + tig * 2;
                    int lp = lp0 + mf * 16 + gid;
                    stage[o*132 + lp]         = C[mf][nf][0];
                    stage[(o+1)*132 + lp]     = C[mf][nf][1];
                    stage[o*132 + lp + 8]     = C[mf][nf][2];
                    stage[(o+1)*132 + lp + 8] = C[mf][nf][3];
                }
        }
        __syncthreads();
        #pragma unroll
        for (int r = 0; r < 16; r++) {
            int idx = r * 512 + t * 2;
            int o = idx >> 7, p = idx & 127;
            __half2 v = __floats2half2_rn(stage[o*132 + p] + bias[o],
                                          stage[o*132 + p + 1] + bias[o]);
            *reinterpret_cast<__half2*>(
                &outp[((size_t)b * CQ + o) * HW + p0 + h*128 + p]) = v;
        }
    }
}

// ---------------------------------------------------------------------------
// energy = K_flat @ Q_flat^T via fp16 m16n8k16 mma, fp32 accum.
// 128 blocks x 2048 d. Per block: 8 tiles of 256 d staged in smem;
// each warp owns 2 k16-steps/tile, full 32x32 accumulators; smem reduce.
__global__ __launch_bounds__(256) void k_energy()
{
    __shared__ __align__(16) char smbuf[34816];
    uint16_t* Kt = (uint16_t*)smbuf;            // [32][264] halves
    uint16_t* Qt = Kt + 32*264;                 // [32][264]
    float* red = (float*)smbuf;                 // [8][1024] (after compute)

    const int t = threadIdx.x;
    const int lane = t & 31;
    const int warp = t >> 5;
    const int gid = lane >> 2, tig = lane & 3;
    const int d0 = blockIdx.x * 2048;
    const uint32_t kt_b = (uint32_t)__cvta_generic_to_shared(Kt);
    const uint32_t qt_b = (uint32_t)__cvta_generic_to_shared(Qt);

    float C[2][4][4];
    #pragma unroll
    for (int mt = 0; mt < 2; mt++)
        #pragma unroll
        for (int nt = 0; nt < 4; nt++)
            #pragma unroll
            for (int i = 0; i < 4; i++) C[mt][nt][i] = 0.0f;

    for (int tile = 0; tile < 8; tile++) {
        const int dt = d0 + tile * 256;
        __syncthreads();
        // fill: 32 rows x 256 halves each of K and Q (coalesced uint4)
        #pragma unroll
        for (int r = 0; r < 4; r++) {
            int idx = r * 256 + t;
            int row = idx >> 5, c4 = idx & 31;
            *reinterpret_cast<uint4*>(&Kt[row*264 + c4*8]) =
                *reinterpret_cast<const uint4*>(&g_Kh[(size_t)row*DD + dt + c4*8]);
            *reinterpret_cast<uint4*>(&Qt[row*264 + c4*8]) =
                *reinterpret_cast<const uint4*>(&g_Qh[(size_t)row*DD + dt + c4*8]);
        }
        __syncthreads();

        #pragma unroll
        for (int ss = 0; ss < 2; ss++) {
            const int ds = (warp * 2 + ss) * 16;
            uint32_t A[2][4];
            #pragma unroll
            for (int mt = 0; mt < 2; mt++) {
                uint32_t addr = kt_b +
                    (uint32_t)(((mt*16 + (lane & 15))*264 + ds + (lane >> 4)*8) * 2);
                ldsm_x4(A[mt][0], A[mt][1], A[mt][2], A[mt][3], addr);
            }
            #pragma unroll
            for (int nt = 0; nt < 4; nt++) {
                uint32_t b0, b1;
                uint32_t addr = qt_b +
                    (uint32_t)(((nt*8 + (lane & 7))*264 + ds + ((lane >> 3) & 1)*8) * 2);
                ldsm_x2(b0, b1, addr);
                #pragma unroll
                for (int mt = 0; mt < 2; mt++)
                    mma_f16(C[mt][nt], A[mt], b0, b1);
            }
        }
    }

    // cross-warp reduction via smem, then one atomicAdd wave
    __syncthreads();
    #pragma unroll
    for (int mt = 0; mt < 2; mt++)
        #pragma unroll
        for (int nt = 0; nt < 4; nt++) {
            int row = mt*16 + gid, col = nt*8 + tig*2;
            float* rw = red + warp*1024;
            rw[row*32 + col]       = C[mt][nt][0];
            rw[row*32 + col + 1]   = C[mt][nt][1];
            rw[(row+8)*32 + col]   = C[mt][nt][2];
            rw[(row+8)*32 + col+1] = C[mt][nt][3];
        }
    __syncthreads();
    #pragma unroll
    for (int r = 0; r < 4; r++) {
        int idx = r * 256 + t;
        float s = 0.f;
        #pragma unroll
        for (int w = 0; w < 8; w++) s += red[w*1024 + idx];
        atomicAdd(&g_energy[idx], s);
    }
}

// ---------------------------------------------------------------------------
__global__ void k_softmax(float* __restrict__ att_out)
{
    int i = threadIdx.x;
    if (i >= BB) return;
    float e[BB];
    float m = -INFINITY;
    #pragma unroll
    for (int j = 0; j < BB; j++) { e[j] = g_energy[i*BB + j]; m = fmaxf(m, e[j]); }
    float s = 0.f;
    #pragma unroll
    for (int j = 0; j < BB; j++) { e[j] = expf(e[j] - m); s += e[j]; }
    float inv = 1.0f / s;
    #pragma unroll
    for (int j = 0; j < BB; j++) {
        float a = e[j] * inv;
        g_att[i*BB + j] = a;
        if (att_out) att_out[i*BB + j] = a;
    }
}

// ---------------------------------------------------------------------------
// y[i,cp] = sum_j att[i,j]*x0[j,cp]; float2 per thread, packed bf16x2 stores.
__global__ __launch_bounds__(256) void k_mix(const float* __restrict__ x0)
{
    __shared__ float att_s[BB*BB];
    const int t = threadIdx.x;
    #pragma unroll
    for (int r = 0; r < 4; r++) att_s[r*256 + t] = g_att[r*256 + t];
    __syncthreads();

    const size_t cp = ((size_t)blockIdx.x * 256 + t) * 2;
    float2 acc[BB];
    #pragma unroll
    for (int i = 0; i < BB; i++) acc[i] = make_float2(0.f, 0.f);

    #pragma unroll
    for (int j = 0; j < BB; j++) {
        float2 v = *reinterpret_cast<const float2*>(&x0[(size_t)j * CHW + cp]);
        #pragma unroll
        for (int i = 0; i < BB; i++) {
            float a = att_s[i*BB + j];
            acc[i].x += a * v.x;
            acc[i].y += a * v.y;
        }
    }
    uint32_t* y2 = (uint32_t*)g_y_bf;
    const size_t base = (size_t)blockIdx.x * 256 + t;
    #pragma unroll
    for (int i = 0; i < BB; i++) {
        __nv_bfloat162 bv = __floats2bfloat162_rn(acc[i].x, acc[i].y);
        y2[(size_t)i * (CHW/2) + base] = *reinterpret_cast<uint32_t*>(&bv);
    }
}

// ---------------------------------------------------------------------------
// out = gamma*(Wv y + bv) + x1 via bf16 m16n8k16 mma + ldmatrix.
// Block: 64 o x 128 p; 8 warps = 2(o) x 4(p); warp tile m32(o) x n32(p).
__global__ __launch_bounds__(256) void k_out_bf16(
    const float* __restrict__ x1, const float* __restrict__ bv,
    const float* __restrict__ gamma, float* __restrict__ outp)
{
    const int b  = blockIdx.y;
    const int ot = blockIdx.z * 64;
    const int p0 = blockIdx.x * 128;
    const int t    = threadIdx.x;
    const int lane = t & 31;
    const int warp = t >> 5;
    const int wo = warp >> 2;
    const int wp = warp & 3;
    const int obase = wo * 32;
    const int pbw   = wp * 32;
    const int gid = lane >> 2;
    const int tig = lane & 3;

    __shared__ __align__(16) uint16_t ws[64*40];
    __shared__ __align__(16) uint16_t ys[32*136];
    const uint32_t ws_b = (uint32_t)__cvta_generic_to_shared(ws);
    const uint32_t ys_b = (uint32_t)__cvta_generic_to_shared(ys);

    float C[2][4][4];
    #pragma unroll
    for (int mf = 0; mf < 2; mf++)
        #pragma unroll
        for (int nf = 0; nf < 4; nf++)
            #pragma unroll
            for (int i = 0; i < 4; i++) C[mf][nf][i] = 0.0f;

    const __nv_bfloat16* ybase = (const __nv_bfloat16*)g_y_bf + (size_t)b * CHW + p0;
    const __nv_bfloat16* wvb   = (const __nv_bfloat16*)g_Wv_bf;

    for (int cc = 0; cc < CC; cc += 32) {
        __syncthreads();
        {
            int row = t >> 2, ch = t & 3;
            *reinterpret_cast<uint4*>(&ws[row*40 + ch*8]) =
                *reinterpret_cast<const uint4*>(wvb + (size_t)(ot + row)*CC + cc + ch*8);
        }
        #pragma unroll
        for (int r = 0; r < 2; r++) {
            int idx = r * 256 + t;
            int row = idx >> 4, ch = idx & 15;
            *reinterpret_cast<uint4*>(&ys[row*136 + ch*8]) =
                *reinterpret_cast<const uint4*>(ybase + (size_t)(cc + row)*HW + ch*8);
        }
        __syncthreads();

        #pragma unroll
        for (int kk = 0; kk < 2; kk++) {
            const int rsel = lane & 15;
            const int half = lane >> 4;
            uint32_t A[2][4];
            #pragma unroll
            for (int mf = 0; mf < 2; mf++) {
                uint32_t addr = ws_b + (uint32_t)((obase + mf*16 + rsel)*80 + kk*32 + half*16);
                ldsm_x4(A[mf][0], A[mf][1], A[mf][2], A[mf][3], addr);
            }
            uint32_t Bf[2][4];
            #pragma unroll
            for (int n2 = 0; n2 < 2; n2++) {
                uint32_t addr = ys_b + (uint32_t)((kk*16 + rsel)*272 + (pbw + n2*16 + half*8)*2);
                ldsm_x4_t(Bf[n2][0], Bf[n2][1], Bf[n2][2], Bf[n2][3], addr);
            }
            #pragma unroll
            for (int mf = 0; mf < 2; mf++)
                #pragma unroll
                for (int nf = 0; nf < 4; nf++)
                    mma_bf16(C[mf][nf], A[mf],
                             Bf[nf>>1][(nf&1)*2], Bf[nf>>1][(nf&1)*2 + 1]);
        }
    }

    const float g = gamma[0];
    #pragma unroll
    for (int mf = 0; mf < 2; mf++) {
        const int o = ot + obase + mf*16 + gid;
        const float bv0 = bv[o], bv1 = bv[o + 8];
        #pragma unroll
        for (int nf = 0; nf < 4; nf++) {
            const int p = p0 + pbw + nf*8 + tig*2;
            size_t gi0 = ((size_t)b * CC + o) * HW + p;
            size_t gi1 = gi0 + (size_t)8 * HW;
            float2 xa = *reinterpret_cast<const float2*>(&x1[gi0]);
            float2 xc = *reinterpret_cast<const float2*>(&x1[gi1]);
            float2 r0, r1;
            r0.x = g * (C[mf][nf][0] + bv0) + xa.x;
            r0.y = g * (C[mf][nf][1] + bv0) + xa.y;
            r1.x = g * (C[mf][nf][2] + bv1) + xc.x;
            r1.y = g * (C[mf][nf][3] + bv1) + xc.y;
            *reinterpret_cast<float2*>(&outp[gi0]) = r0;
            *reinterpret_cast<float2*>(&outp[gi1]) = r1;
        }
    }
}

// ---------------------------------------------------------------------------
extern "C" void kernel_launch(void* const* d_in, const int* in_sizes, int n_in,
                              void* d_out, int out_size)
{
    const float* x0    = (const float*)d_in[0];
    const float* x1    = (const float*)d_in[1];
    const float* Wq    = (const float*)d_in[2];
    const float* bq    = (const float*)d_in[3];
    const float* Wk    = (const float*)d_in[4];
    const float* bk    = (const float*)d_in[5];
    const float* Wv    = (const float*)d_in[6];
    const float* bv    = (const float*)d_in[7];
    const float* gamma = (const float*)d_in[8];
    float* out = (float*)d_out;

    const long long out_elems = (long long)BB * CC * HW;
    float* att_out = ((long long)out_size >= out_elems + BB*BB)
                     ? out + out_elems : nullptr;

    k_prep<<<32, 256>>>(Wq, Wk, Wv);
    k_zero_energy<<<1, 1024>>>();
    k_proj_tf32<<<dim3(HW/256, BB, 2), 256>>>(x0, x1, bq, bk);
    k_energy<<<DD/2048, 256>>>();
    k_softmax<<<1, 32>>>(att_out);
    k_mix<<<CHW/512, 256>>>(x0);
    k_out_bf16<<<dim3(HW/128, BB, CC/64), 256>>>(x1, bv, gamma, out);
}

// round 12
// speedup vs baseline: 1.4932x; 1.1001x over previous
#include <cuda_runtime.h>
#include <cuda_bf16.h>
#include <cuda_fp16.h>
#include <math.h>
#include <stdint.h>

#define BB   32
#define CC   256
#define CQ   64
#define HW   4096
#define CHW  (CC*HW)
#define DD   (CQ*HW)

__device__ __half g_Qh[(size_t)BB*DD];
__device__ __half g_Kh[(size_t)BB*DD];
__device__ float g_energy[BB*BB];
__device__ float g_att[BB*BB];
__device__ uint4 g_y_bf[(size_t)BB*CHW/8];     // bf16 [i][c][p]
__device__ uint4 g_Wv_bf[CC*CC/8];             // bf16 [o][c]
__device__ uint16_t g_Wqk[2*128*256];          // bf16 [w][ (Wh;Wl) 128 rows ][c]

// ---------------------------------------------------------------------------
__device__ __forceinline__ void mma_bf16(
    float* c, const uint32_t* a, uint32_t b0, uint32_t b1)
{
    asm volatile(
        "mma.sync.aligned.m16n8k16.row.col.f32.bf16.bf16.f32 "
        "{%0,%1,%2,%3}, {%4,%5,%6,%7}, {%8,%9}, {%0,%1,%2,%3};"
        : "+f"(c[0]), "+f"(c[1]), "+f"(c[2]), "+f"(c[3])
        : "r"(a[0]), "r"(a[1]), "r"(a[2]), "r"(a[3]), "r"(b0), "r"(b1));
}
__device__ __forceinline__ void mma_f16(
    float* c, const uint32_t* a, uint32_t b0, uint32_t b1)
{
    asm volatile(
        "mma.sync.aligned.m16n8k16.row.col.f32.f16.f16.f32 "
        "{%0,%1,%2,%3}, {%4,%5,%6,%7}, {%8,%9}, {%0,%1,%2,%3};"
        : "+f"(c[0]), "+f"(c[1]), "+f"(c[2]), "+f"(c[3])
        : "r"(a[0]), "r"(a[1]), "r"(a[2]), "r"(a[3]), "r"(b0), "r"(b1));
}
__device__ __forceinline__ void ldsm_x4(
    uint32_t& r0, uint32_t& r1, uint32_t& r2, uint32_t& r3, uint32_t addr)
{
    asm volatile("ldmatrix.sync.aligned.m8n8.x4.shared.b16 {%0,%1,%2,%3}, [%4];"
        : "=r"(r0), "=r"(r1), "=r"(r2), "=r"(r3) : "r"(addr));
}
__device__ __forceinline__ void ldsm_x2(
    uint32_t& r0, uint32_t& r1, uint32_t addr)
{
    asm volatile("ldmatrix.sync.aligned.m8n8.x2.shared.b16 {%0,%1}, [%2];"
        : "=r"(r0), "=r"(r1) : "r"(addr));
}
__device__ __forceinline__ void ldsm_x4_t(
    uint32_t& r0, uint32_t& r1, uint32_t& r2, uint32_t& r3, uint32_t addr)
{
    asm volatile("ldmatrix.sync.aligned.m8n8.x4.trans.shared.b16 {%0,%1,%2,%3}, [%4];"
        : "=r"(r0), "=r"(r1), "=r"(r2), "=r"(r3) : "r"(addr));
}
__device__ __forceinline__ uint16_t bfb(__nv_bfloat16 h) {
    uint16_t u; memcpy(&u, &h, 2); return u;
}

// ---------------------------------------------------------------------------
// Prep: Wq/Wk -> stacked [bf16(W); residual] 128x256 rows; Wv -> bf16 [o][c].
__global__ __launch_bounds__(256) void k_prep(
    const float* __restrict__ Wq, const float* __restrict__ Wk,
    const float* __restrict__ Wv)
{
    int t = blockIdx.x * 256 + threadIdx.x;
    int stride = gridDim.x * 256;
    for (int i = t; i < 2*CQ*CC; i += stride) {
        int w = i >> 14, rem = i & 16383;
        int o = rem >> 8, c = rem & 255;
        float f = (w ? Wk : Wq)[o*CC + c];
        __nv_bfloat16 h = __float2bfloat16(f);
        __nv_bfloat16 l = __float2bfloat16(f - __bfloat162float(h));
        g_Wqk[w*32768 + o*CC + c]        = bfb(h);
        g_Wqk[w*32768 + (o+64)*CC + c]   = bfb(l);
    }
    __nv_bfloat16* wv = (__nv_bfloat16*)g_Wv_bf;
    for (int i = t; i < CC*CC; i += stride)
        wv[i] = __float2bfloat16(Wv[i]);
}

// ---------------------------------------------------------------------------
__global__ void k_zero_energy() {
    int t = threadIdx.x;
    if (t < BB*BB) g_energy[t] = 0.0f;
}

// ---------------------------------------------------------------------------
// Q/K projection: D[128][64p] = [Wh;Wl] @ (xh + xl), two accumulating passes.
// out[o] = D[o] + D[o+64] + bias. 8 warps = 4(m32) x 2(n32).
__global__ __launch_bounds__(256) void k_proj_bf16(
    const float* __restrict__ x0, const float* __restrict__ x1,
    const float* __restrict__ bq, const float* __restrict__ bk)
{
    const int which = blockIdx.z;
    const int b  = blockIdx.y;
    const int p0 = blockIdx.x * 64;
    const float* __restrict__ x    = which ? x1 : x0;
    const float* __restrict__ bias = which ? bk : bq;
    __half* __restrict__ outp      = which ? g_Kh : g_Qh;

    const int t = threadIdx.x;
    const int lane = t & 31, warp = t >> 5;
    const int mg = warp >> 1;          // 0..3  (m-group of 32)
    const int np = warp & 1;           // 0..1  (n-group of 32)
    const int rsel = lane & 15, half = lane >> 4;
    const int gid = lane >> 2, tig = lane & 3;

    __shared__ __align__(16) char smraw[33792];
    uint16_t* ws = (uint16_t*)smraw;               // [128][40]  10240B
    uint16_t* xh = (uint16_t*)(smraw + 10240);     // [32][136]  8704B
    uint16_t* xl = (uint16_t*)(smraw + 18944);     // [32][136]  8704B
    float* stage = (float*)smraw;                  // [128][66]  33792B (reuse)
    const uint32_t ws_b = (uint32_t)__cvta_generic_to_shared(ws);
    const uint32_t xh_b = (uint32_t)__cvta_generic_to_shared(xh);
    const uint32_t xl_b = (uint32_t)__cvta_generic_to_shared(xl);

    float C[2][4][4];
    #pragma unroll
    for (int mf = 0; mf < 2; mf++)
        #pragma unroll
        for (int nf = 0; nf < 4; nf++)
            #pragma unroll
            for (int i = 0; i < 4; i++) C[mf][nf][i] = 0.0f;

    const uint16_t* wsrc = g_Wqk + which*32768;
    const float* xb = x + (size_t)b * CHW + p0;

    for (int cc = 0; cc < CC; cc += 32) {
        __syncthreads();
        // ws: 128 rows x 32 c (512 uint4, 2/thread)
        #pragma unroll
        for (int r = 0; r < 2; r++) {
            int idx = r * 256 + t;
            int row = idx >> 2, c8 = idx & 3;
            *reinterpret_cast<uint4*>(&ws[row*40 + c8*8]) =
                *reinterpret_cast<const uint4*>(&wsrc[row*CC + cc + c8*8]);
        }
        // x tile 32c x 64p fp32 -> bf16 hi/lo (512 float4, 2/thread)
        #pragma unroll
        for (int r = 0; r < 2; r++) {
            int idx = r * 256 + t;
            int c = idx >> 4, p4 = idx & 15;
            float4 v = *reinterpret_cast<const float4*>(
                xb + (size_t)(cc + c) * HW + p4 * 4);
            __nv_bfloat16 h0 = __float2bfloat16(v.x), h1 = __float2bfloat16(v.y);
            __nv_bfloat16 h2 = __float2bfloat16(v.z), h3 = __float2bfloat16(v.w);
            uint2 hp, lp;
            hp.x = (uint32_t)bfb(h0) | ((uint32_t)bfb(h1) << 16);
            hp.y = (uint32_t)bfb(h2) | ((uint32_t)bfb(h3) << 16);
            lp.x = (uint32_t)bfb(__float2bfloat16(v.x - __bfloat162float(h0)))
                 | ((uint32_t)bfb(__float2bfloat16(v.y - __bfloat162float(h1))) << 16);
            lp.y = (uint32_t)bfb(__float2bfloat16(v.z - __bfloat162float(h2)))
                 | ((uint32_t)bfb(__float2bfloat16(v.w - __bfloat162float(h3))) << 16);
            *reinterpret_cast<uint2*>(&xh[c*136 + p4*4]) = hp;
            *reinterpret_cast<uint2*>(&xl[c*136 + p4*4]) = lp;
        }
        __syncthreads();

        #pragma unroll
        for (int kk = 0; kk < 2; kk++) {
            uint32_t A[2][4];
            #pragma unroll
            for (int mf = 0; mf < 2; mf++) {
                uint32_t addr = ws_b +
                    (uint32_t)((mg*32 + mf*16 + rsel)*80 + kk*32 + half*16);
                ldsm_x4(A[mf][0], A[mf][1], A[mf][2], A[mf][3], addr);
            }
            uint32_t Bh[2][4], Bl[2][4];
            #pragma unroll
            for (int n2 = 0; n2 < 2; n2++) {
                uint32_t off = (uint32_t)((kk*16 + rsel)*272 + (np*32 + n2*16 + half*8)*2);
                ldsm_x4_t(Bh[n2][0], Bh[n2][1], Bh[n2][2], Bh[n2][3], xh_b + off);
                ldsm_x4_t(Bl[n2][0], Bl[n2][1], Bl[n2][2], Bl[n2][3], xl_b + off);
            }
            #pragma unroll
            for (int mf = 0; mf < 2; mf++)
                #pragma unroll
                for (int nf = 0; nf < 4; nf++) {
                    mma_bf16(C[mf][nf], A[mf],
                             Bh[nf>>1][(nf&1)*2], Bh[nf>>1][(nf&1)*2 + 1]);
                    mma_bf16(C[mf][nf], A[mf],
                             Bl[nf>>1][(nf&1)*2], Bl[nf>>1][(nf&1)*2 + 1]);
                }
        }
    }

    // Stage all 128 rows, then combine o and o+64
    __syncthreads();
    #pragma unroll
    for (int mf = 0; mf < 2; mf++)
        #pragma unroll
        for (int nf = 0; nf < 4; nf++) {
            int row = mg*32 + mf*16 + gid;
            int col = np*32 + nf*8 + tig*2;
            stage[row*66 + col]       = C[mf][nf][0];
            stage[row*66 + col + 1]   = C[mf][nf][1];
            stage[(row+8)*66 + col]   = C[mf][nf][2];
            stage[(row+8)*66 + col+1] = C[mf][nf][3];
        }
    __syncthreads();
    #pragma unroll
    for (int r = 0; r < 8; r++) {
        int idx = r * 512 + t * 2;
        int o = idx >> 6, p = idx & 63;
        float bb = bias[o];
        __half2 v = __floats2half2_rn(
            stage[o*66 + p]     + stage[(o+64)*66 + p]     + bb,
            stage[o*66 + p + 1] + stage[(o+64)*66 + p + 1] + bb);
        *reinterpret_cast<__half2*>(&outp[((size_t)b*CQ + o)*HW + p0 + p]) = v;
    }
}

// ---------------------------------------------------------------------------
// energy via fp16 mma (unchanged from R10 — measured 18us)
__global__ __launch_bounds__(256) void k_energy()
{
    __shared__ __align__(16) char smbuf[34816];
    uint16_t* Kt = (uint16_t*)smbuf;
    uint16_t* Qt = Kt + 32*264;
    float* red = (float*)smbuf;

    const int t = threadIdx.x;
    const int lane = t & 31, warp = t >> 5;
    const int gid = lane >> 2, tig = lane & 3;
    const int d0 = blockIdx.x * 2048;
    const uint32_t kt_b = (uint32_t)__cvta_generic_to_shared(Kt);
    const uint32_t qt_b = (uint32_t)__cvta_generic_to_shared(Qt);

    float C[2][4][4];
    #pragma unroll
    for (int mt = 0; mt < 2; mt++)
        #pragma unroll
        for (int nt = 0; nt < 4; nt++)
            #pragma unroll
            for (int i = 0; i < 4; i++) C[mt][nt][i] = 0.0f;

    for (int tile = 0; tile < 8; tile++) {
        const int dt = d0 + tile * 256;
        __syncthreads();
        #pragma unroll
        for (int r = 0; r < 4; r++) {
            int idx = r * 256 + t;
            int row = idx >> 5, c4 = idx & 31;
            *reinterpret_cast<uint4*>(&Kt[row*264 + c4*8]) =
                *reinterpret_cast<const uint4*>(&g_Kh[(size_t)row*DD + dt + c4*8]);
            *reinterpret_cast<uint4*>(&Qt[row*264 + c4*8]) =
                *reinterpret_cast<const uint4*>(&g_Qh[(size_t)row*DD + dt + c4*8]);
        }
        __syncthreads();
        #pragma unroll
        for (int ss = 0; ss < 2; ss++) {
            const int ds = (warp * 2 + ss) * 16;
            uint32_t A[2][4];
            #pragma unroll
            for (int mt = 0; mt < 2; mt++) {
                uint32_t addr = kt_b +
                    (uint32_t)(((mt*16 + (lane & 15))*264 + ds + (lane >> 4)*8) * 2);
                ldsm_x4(A[mt][0], A[mt][1], A[mt][2], A[mt][3], addr);
            }
            #pragma unroll
            for (int nt = 0; nt < 4; nt++) {
                uint32_t b0, b1;
                uint32_t addr = qt_b +
                    (uint32_t)(((nt*8 + (lane & 7))*264 + ds + ((lane >> 3) & 1)*8) * 2);
                ldsm_x2(b0, b1, addr);
                #pragma unroll
                for (int mt = 0; mt < 2; mt++)
                    mma_f16(C[mt][nt], A[mt], b0, b1);
            }
        }
    }
    __syncthreads();
    #pragma unroll
    for (int mt = 0; mt < 2; mt++)
        #pragma unroll
        for (int nt = 0; nt < 4; nt++) {
            int row = mt*16 + gid, col = nt*8 + tig*2;
            float* rw = red + warp*1024;
            rw[row*32 + col]       = C[mt][nt][0];
            rw[row*32 + col + 1]   = C[mt][nt][1];
            rw[(row+8)*32 + col]   = C[mt][nt][2];
            rw[(row+8)*32 + col+1] = C[mt][nt][3];
        }
    __syncthreads();
    #pragma unroll
    for (int r = 0; r < 4; r++) {
        int idx = r * 256 + t;
        float s = 0.f;
        #pragma unroll
        for (int w = 0; w < 8; w++) s += red[w*1024 + idx];
        atomicAdd(&g_energy[idx], s);
    }
}

// ---------------------------------------------------------------------------
__global__ void k_softmax(float* __restrict__ att_out)
{
    int i = threadIdx.x;
    if (i >= BB) return;
    float e[BB];
    float m = -INFINITY;
    #pragma unroll
    for (int j = 0; j < BB; j++) { e[j] = g_energy[i*BB + j]; m = fmaxf(m, e[j]); }
    float s = 0.f;
    #pragma unroll
    for (int j = 0; j < BB; j++) { e[j] = expf(e[j] - m); s += e[j]; }
    float inv = 1.0f / s;
    #pragma unroll
    for (int j = 0; j < BB; j++) {
        float a = e[j] * inv;
        g_att[i*BB + j] = a;
        if (att_out) att_out[i*BB + j] = a;
    }
}

// ---------------------------------------------------------------------------
__global__ __launch_bounds__(256) void k_mix(const float* __restrict__ x0)
{
    __shared__ float att_s[BB*BB];
    const int t = threadIdx.x;
    #pragma unroll
    for (int r = 0; r < 4; r++) att_s[r*256 + t] = g_att[r*256 + t];
    __syncthreads();

    const size_t cp = ((size_t)blockIdx.x * 256 + t) * 2;
    float2 acc[BB];
    #pragma unroll
    for (int i = 0; i < BB; i++) acc[i] = make_float2(0.f, 0.f);

    #pragma unroll
    for (int j = 0; j < BB; j++) {
        float2 v = *reinterpret_cast<const float2*>(&x0[(size_t)j * CHW + cp]);
        #pragma unroll
        for (int i = 0; i < BB; i++) {
            float a = att_s[i*BB + j];
            acc[i].x += a * v.x;
            acc[i].y += a * v.y;
        }
    }
    uint32_t* y2 = (uint32_t*)g_y_bf;
    const size_t base = (size_t)blockIdx.x * 256 + t;
    #pragma unroll
    for (int i = 0; i < BB; i++) {
        __nv_bfloat162 bv = __floats2bfloat162_rn(acc[i].x, acc[i].y);
        y2[(size_t)i * (CHW/2) + base] = *reinterpret_cast<uint32_t*>(&bv);
    }
}

// ---------------------------------------------------------------------------
__global__ __launch_bounds__(256) void k_out_bf16(
    const float* __restrict__ x1, const float* __restrict__ bv,
    const float* __restrict__ gamma, float* __restrict__ outp)
{
    const int b  = blockIdx.y;
    const int ot = blockIdx.z * 64;
    const int p0 = blockIdx.x * 128;
    const int t    = threadIdx.x;
    const int lane = t & 31, warp = t >> 5;
    const int wo = warp >> 2, wp = warp & 3;
    const int obase = wo * 32, pbw = wp * 32;
    const int gid = lane >> 2, tig = lane & 3;

    __shared__ __align__(16) uint16_t ws[64*40];
    __shared__ __align__(16) uint16_t ys[32*136];
    const uint32_t ws_b = (uint32_t)__cvta_generic_to_shared(ws);
    const uint32_t ys_b = (uint32_t)__cvta_generic_to_shared(ys);

    float C[2][4][4];
    #pragma unroll
    for (int mf = 0; mf < 2; mf++)
        #pragma unroll
        for (int nf = 0; nf < 4; nf++)
            #pragma unroll
            for (int i = 0; i < 4; i++) C[mf][nf][i] = 0.0f;

    const __nv_bfloat16* ybase = (const __nv_bfloat16*)g_y_bf + (size_t)b * CHW + p0;
    const __nv_bfloat16* wvb   = (const __nv_bfloat16*)g_Wv_bf;

    for (int cc = 0; cc < CC; cc += 32) {
        __syncthreads();
        {
            int row = t >> 2, ch = t & 3;
            *reinterpret_cast<uint4*>(&ws[row*40 + ch*8]) =
                *reinterpret_cast<const uint4*>(wvb + (size_t)(ot + row)*CC + cc + ch*8);
        }
        #pragma unroll
        for (int r = 0; r < 2; r++) {
            int idx = r * 256 + t;
            int row = idx >> 4, ch = idx & 15;
            *reinterpret_cast<uint4*>(&ys[row*136 + ch*8]) =
                *reinterpret_cast<const uint4*>(ybase + (size_t)(cc + row)*HW + ch*8);
        }
        __syncthreads();

        #pragma unroll
        for (int kk = 0; kk < 2; kk++) {
            const int rsel = lane & 15;
            const int half = lane >> 4;
            uint32_t A[2][4];
            #pragma unroll
            for (int mf = 0; mf < 2; mf++) {
                uint32_t addr = ws_b + (uint32_t)((obase + mf*16 + rsel)*80 + kk*32 + half*16);
                ldsm_x4(A[mf][0], A[mf][1], A[mf][2], A[mf][3], addr);
            }
            uint32_t Bf[2][4];
            #pragma unroll
            for (int n2 = 0; n2 < 2; n2++) {
                uint32_t addr = ys_b + (uint32_t)((kk*16 + rsel)*272 + (pbw + n2*16 + half*8)*2);
                ldsm_x4_t(Bf[n2][0], Bf[n2][1], Bf[n2][2], Bf[n2][3], addr);
            }
            #pragma unroll
            for (int mf = 0; mf < 2; mf++)
                #pragma unroll
                for (int nf = 0; nf < 4; nf++)
                    mma_bf16(C[mf][nf], A[mf],
                             Bf[nf>>1][(nf&1)*2], Bf[nf>>1][(nf&1)*2 + 1]);
        }
    }

    const float g = gamma[0];
    #pragma unroll
    for (int mf = 0; mf < 2; mf++) {
        const int o = ot + obase + mf*16 + gid;
        const float bv0 = bv[o], bv1 = bv[o + 8];
        #pragma unroll
        for (int nf = 0; nf < 4; nf++) {
            const int p = p0 + pbw + nf*8 + tig*2;
            size_t gi0 = ((size_t)b * CC + o) * HW + p;
            size_t gi1 = gi0 + (size_t)8 * HW;
            float2 xa = *reinterpret_cast<const float2*>(&x1[gi0]);
            float2 xc = *reinterpret_cast<const float2*>(&x1[gi1]);
            float2 r0, r1;
            r0.x = g * (C[mf][nf][0] + bv0) + xa.x;
            r0.y = g * (C[mf][nf][1] + bv0) + xa.y;
            r1.x = g * (C[mf][nf][2] + bv1) + xc.x;
            r1.y = g * (C[mf][nf][3] + bv1) + xc.y;
            *reinterpret_cast<float2*>(&outp[gi0]) = r0;
            *reinterpret_cast<float2*>(&outp[gi1]) = r1;
        }
    }
}

// ---------------------------------------------------------------------------
extern "C" void kernel_launch(void* const* d_in, const int* in_sizes, int n_in,
                              void* d_out, int out_size)
{
    const float* x0    = (const float*)d_in[0];
    const float* x1    = (const float*)d_in[1];
    const float* Wq    = (const float*)d_in[2];
    const float* bq    = (const float*)d_in[3];
    const float* Wk    = (const float*)d_in[4];
    const float* bk    = (const float*)d_in[5];
    const float* Wv    = (const float*)d_in[6];
    const float* bv    = (const float*)d_in[7];
    const float* gamma = (const float*)d_in[8];
    float* out = (float*)d_out;

    const long long out_elems = (long long)BB * CC * HW;
    float* att_out = ((long long)out_size >= out_elems + BB*BB)
                     ? out + out_elems : nullptr;

    k_prep<<<32, 256>>>(Wq, Wk, Wv);
    k_zero_energy<<<1, 1024>>>();
    k_proj_bf16<<<dim3(HW/64, BB, 2), 256>>>(x0, x1, bq, bk);
    k_energy<<<DD/2048, 256>>>();
    k_softmax<<<1, 32>>>(att_out);
    k_mix<<<CHW/512, 256>>>(x0);
    k_out_bf16<<<dim3(HW/128, BB, CC/64), 256>>>(x1, bv, gamma, out);
}